// round 5
// baseline (speedup 1.0000x reference)
#include <cuda_runtime.h>
#include <cstdint>

#define NN 200000
#define CC 256
#define MM 50000
#define VCD 48   // 16 vector channels * 3 spatial dims

// Scratch accumulators (device globals; no allocation allowed in kernel_launch)
__device__ float g_s_sum[(size_t)MM * CC];   // 51.2 MB
__device__ float g_v_sum[(size_t)MM * VCD];  // 9.6 MB
__device__ float g_cnt[MM];
__device__ int   g_seg_is64;

// ============================ helpers ======================================
__device__ __forceinline__ uint32_t smem_u32(const void* p) {
    uint32_t a;
    asm("{ .reg .u64 t; cvta.to.shared.u64 t, %1; cvt.u32.u64 %0, t; }"
        : "=r"(a) : "l"(p));
    return a;
}
__device__ __forceinline__ float to_tf32(float x) {
    float r;
    asm("cvt.rna.tf32.f32 %0, %1;" : "=f"(r) : "f"(x));
    return r;
}
__device__ __forceinline__ void ldsm_x4(uint32_t* r, uint32_t addr) {
    asm volatile("ldmatrix.sync.aligned.m8n8.x4.shared.b16 {%0,%1,%2,%3}, [%4];"
        : "=r"(r[0]), "=r"(r[1]), "=r"(r[2]), "=r"(r[3]) : "r"(addr));
}
__device__ __forceinline__ void ldsm_x2(uint32_t* r, uint32_t addr) {
    asm volatile("ldmatrix.sync.aligned.m8n8.x2.shared.b16 {%0,%1}, [%2];"
        : "=r"(r[0]), "=r"(r[1]) : "r"(addr));
}
__device__ __forceinline__ void mma_tf32(float* c, const uint32_t* a, const uint32_t* b) {
    asm volatile(
        "mma.sync.aligned.m16n8k8.row.col.f32.tf32.tf32.f32 "
        "{%0,%1,%2,%3}, {%4,%5,%6,%7}, {%8,%9}, {%0,%1,%2,%3};"
        : "+f"(c[0]), "+f"(c[1]), "+f"(c[2]), "+f"(c[3])
        : "r"(a[0]), "r"(a[1]), "r"(a[2]), "r"(a[3]), "r"(b[0]), "r"(b[1]));
}
__device__ __forceinline__ void cp_async16(uint32_t saddr, const void* gaddr,
                                           uint32_t src_size) {
    asm volatile("cp.async.ca.shared.global [%0], [%1], 16, %2;"
                 :: "r"(saddr), "l"(gaddr), "r"(src_size) : "memory");
}
__device__ __forceinline__ void red_add_v4(float* addr, float4 val) {
    asm volatile("red.global.add.v4.f32 [%0], {%1,%2,%3,%4};"
                 :: "l"(addr), "f"(val.x), "f"(val.y), "f"(val.z), "f"(val.w)
                 : "memory");
}

// ---------------------------------------------------------------------------
// Probe the segment-index buffer's dtype (int64 vs int32).
// ---------------------------------------------------------------------------
__global__ void probe_seg_kernel(const int* __restrict__ seg32) {
    __shared__ int any_nonzero;
    if (threadIdx.x == 0) any_nonzero = 0;
    __syncthreads();
    for (int i = threadIdx.x; i < 1024; i += blockDim.x)
        if (seg32[2 * i + 1] != 0) any_nonzero = 1;
    __syncthreads();
    if (threadIdx.x == 0) g_seg_is64 = (any_nonzero == 0) ? 1 : 0;
}
__device__ __forceinline__ int load_seg(const void* seg, int n, int is64) {
    if (is64) return (int)((const long long*)seg)[n];
    return ((const int*)seg)[n];
}

// ---------------------------------------------------------------------------
__global__ void zero_kernel() {
    size_t i = blockIdx.x * (size_t)blockDim.x + threadIdx.x;
    size_t stride = (size_t)gridDim.x * blockDim.x;
    float4 z = make_float4(0.f, 0.f, 0.f, 0.f);
    float4* ps = (float4*)g_s_sum;
    size_t ns = (size_t)MM * CC / 4;
    for (size_t j = i; j < ns; j += stride) ps[j] = z;
    float4* pv = (float4*)g_v_sum;
    size_t nv = (size_t)MM * VCD / 4;
    for (size_t j = i; j < nv; j += stride) pv[j] = z;
    for (size_t j = i; j < MM; j += stride) g_cnt[j] = 0.f;
}

__global__ void scatter_s_kernel(const float* __restrict__ s,
                                 const void* __restrict__ seg) {
    long long i = blockIdx.x * (long long)blockDim.x + threadIdx.x;
    if (i >= (long long)NN * (CC / 4)) return;
    int n  = (int)(i >> 6);
    int c4 = (int)(i & 63);
    int m = load_seg(seg, n, g_seg_is64);
    if ((unsigned)m >= MM) return;
    float4 val = ((const float4*)s)[i];
    red_add_v4(&g_s_sum[(size_t)m * CC + c4 * 4], val);
}

__global__ void scatter_v_kernel(const float* __restrict__ v,
                                 const void* __restrict__ seg) {
    long long i = blockIdx.x * (long long)blockDim.x + threadIdx.x;
    if (i >= (long long)NN * (VCD / 4)) return;
    int n  = (int)(i / 12);
    int j4 = (int)(i % 12);
    int m = load_seg(seg, n, g_seg_is64);
    if ((unsigned)m >= MM) return;
    float4 val = ((const float4*)v)[i];
    red_add_v4(&g_v_sum[(size_t)m * VCD + j4 * 4], val);
    if (j4 == 0) atomicAdd(&g_cnt[m], 1.0f);
}

// ---------------------------------------------------------------------------
// tf32 mma.sync GEMM, 2xTF32 A-split done in REGISTERS, cp.async double buffer.
// BM=128, BN=128, BK=32. 8 warps 2(M)x4(N), each 64x32 via 4x4 m16n8k8 frags.
// SMEM raw tiles [row][32 floats], 16B chunks XOR-swizzled (q ^ row&7).
// ---------------------------------------------------------------------------
#define SMO_INVC 0
#define SMO_BS   512
#define SMO_A    1024                 // 2 stages x 16KB
#define SMO_B    (1024 + 32768)       // 2 stages x 16KB
#define SMO_TOTAL (1024 + 65536)

__global__ void __launch_bounds__(256, 2)
gemm_s_mma(const float* __restrict__ Ws, const float* __restrict__ bs,
           float* __restrict__ out) {
    extern __shared__ char sm[];
    uint32_t sb = smem_u32(sm);
    int tid = threadIdx.x, wid = tid >> 5, lane = tid & 31;
    int wm = wid & 1, wn = wid >> 1;
    int m0 = blockIdx.y * 128, n0 = blockIdx.x * 128;

    float* invc = (float*)(sm + SMO_INVC);
    float* bssh = (float*)(sm + SMO_BS);
    if (tid < 128) {
        int gm = m0 + tid;
        float c = (gm < MM) ? g_cnt[gm] : 1.0f;
        invc[tid] = 1.0f / fmaxf(c, 1.0f);
        bssh[tid] = bs[n0 + tid];
    }
    __syncthreads();

    // ---- per-thread cp.async source/dest precompute (4 A chunks, 4 B chunks)
    const float* gA[4]; const float* gB[4];
    uint32_t offAB[4]; uint32_t szA[4];
#pragma unroll
    for (int i = 0; i < 4; i++) {
        int f = tid + 256 * i;
        int row = f >> 3, q = f & 7;
        int gm = m0 + row;
        bool ok = (gm < MM);
        gA[i] = g_s_sum + (size_t)(ok ? gm : 0) * CC + q * 4;
        szA[i] = ok ? 16u : 0u;
        gB[i] = Ws + (size_t)(n0 + row) * CC + q * 4;
        offAB[i] = row * 128 + ((q ^ (row & 7)) << 4);
    }

    // ---- per-warp fragment addresses
    int r8 = lane & 7;
    int halfA = (lane >> 3) & 1;
    int ksubA = lane >> 4;
    int ksubB = (lane >> 3) & 1;
    int lr = lane >> 2;
    uint32_t aRowOff[4]; int aRsw[4];
    float invA0[4], invA1[4];
#pragma unroll
    for (int mi = 0; mi < 4; mi++) {
        int rbase = wm * 64 + mi * 16;
        int row = rbase + halfA * 8 + r8;
        aRowOff[mi] = row * 128;
        aRsw[mi] = row & 7;
        invA0[mi] = invc[rbase + lr];
        invA1[mi] = invc[rbase + lr + 8];
    }
    uint32_t bRowOff[4];
#pragma unroll
    for (int ni = 0; ni < 4; ni++)
        bRowOff[ni] = (wn * 32 + ni * 8 + r8) * 128;

    float acc[4][4][4];
#pragma unroll
    for (int a = 0; a < 4; a++)
#pragma unroll
        for (int b = 0; b < 4; b++)
#pragma unroll
            for (int c = 0; c < 4; c++) acc[a][b][c] = 0.f;

#define LOAD_TILES(CH, ST)                                                    \
    {                                                                         \
        uint32_t ab = sb + SMO_A + (ST) * 16384;                              \
        uint32_t bb = sb + SMO_B + (ST) * 16384;                              \
        int kt = (CH) * 32;                                                   \
        _Pragma("unroll")                                                     \
        for (int i = 0; i < 4; i++) cp_async16(ab + offAB[i], gA[i] + kt, szA[i]); \
        _Pragma("unroll")                                                     \
        for (int i = 0; i < 4; i++) cp_async16(bb + offAB[i], gB[i] + kt, 16u);    \
        asm volatile("cp.async.commit_group;" ::: "memory");                  \
    }

    LOAD_TILES(0, 0)

    for (int ch = 0; ch < 8; ch++) {
        if (ch < 7) {
            LOAD_TILES(ch + 1, (ch + 1) & 1)
            asm volatile("cp.async.wait_group 1;" ::: "memory");
        } else {
            asm volatile("cp.async.wait_group 0;" ::: "memory");
        }
        __syncthreads();

        uint32_t ab = sb + SMO_A + (ch & 1) * 16384;
        uint32_t bb = sb + SMO_B + (ch & 1) * 16384;
#pragma unroll
        for (int ks = 0; ks < 4; ks++) {
            int ks2 = ks * 2;
            uint32_t bf[4][2];
#pragma unroll
            for (int ni = 0; ni < 4; ni++) {
                ldsm_x2(bf[ni], bb + bRowOff[ni] + (((ks2 + ksubB) ^ r8) << 4));
                bf[ni][0] = __float_as_uint(to_tf32(__uint_as_float(bf[ni][0])));
                bf[ni][1] = __float_as_uint(to_tf32(__uint_as_float(bf[ni][1])));
            }
#pragma unroll
            for (int mi = 0; mi < 4; mi++) {
                uint32_t ar[4], ah[4], al[4];
                uint32_t ca = ((uint32_t)((ks2 + ksubA) ^ aRsw[mi])) << 4;
                ldsm_x4(ar, ab + aRowOff[mi] + ca);
                float f0 = __uint_as_float(ar[0]) * invA0[mi];
                float f1 = __uint_as_float(ar[1]) * invA1[mi];
                float f2 = __uint_as_float(ar[2]) * invA0[mi];
                float f3 = __uint_as_float(ar[3]) * invA1[mi];
                float h0 = to_tf32(f0), h1 = to_tf32(f1);
                float h2 = to_tf32(f2), h3 = to_tf32(f3);
                ah[0] = __float_as_uint(h0); ah[1] = __float_as_uint(h1);
                ah[2] = __float_as_uint(h2); ah[3] = __float_as_uint(h3);
                al[0] = __float_as_uint(f0 - h0); al[1] = __float_as_uint(f1 - h1);
                al[2] = __float_as_uint(f2 - h2); al[3] = __float_as_uint(f3 - h3);
#pragma unroll
                for (int ni = 0; ni < 4; ni++) {
                    mma_tf32(acc[mi][ni], ah, bf[ni]);
                    mma_tf32(acc[mi][ni], al, bf[ni]);
                }
            }
        }
        __syncthreads();
    }

    // ---- epilogue
    int lc2 = 2 * (lane & 3);
#pragma unroll
    for (int mi = 0; mi < 4; mi++) {
#pragma unroll
        for (int ni = 0; ni < 4; ni++) {
            int lcol = wn * 32 + ni * 8 + lc2;
            float b0 = bssh[lcol], b1 = bssh[lcol + 1];
            int row0 = m0 + wm * 64 + mi * 16 + lr;
            if (row0 < MM) {
                float2 o = make_float2(acc[mi][ni][0] + b0, acc[mi][ni][1] + b1);
                *(float2*)(out + (size_t)row0 * CC + n0 + lcol) = o;
            }
            int row1 = row0 + 8;
            if (row1 < MM) {
                float2 o = make_float2(acc[mi][ni][2] + b0, acc[mi][ni][3] + b1);
                *(float2*)(out + (size_t)row1 * CC + n0 + lcol) = o;
            }
        }
    }
}

// ---------------------------------------------------------------------------
__global__ void v_out_kernel(const float* __restrict__ Wv,
                             const float* __restrict__ bv,
                             float* __restrict__ out_v) {
    int i = blockIdx.x * blockDim.x + threadIdx.x;
    if (i >= MM * VCD) return;
    int m = i / 48;
    int r = i % 48;
    int o = r / 3, d = r % 3;
    float inv = 1.0f / fmaxf(g_cnt[m], 1.0f);
    const float* vm = g_v_sum + (size_t)m * 48;
    const float* w  = Wv + o * 16;
    float sum = 0.f;
#pragma unroll
    for (int c = 0; c < 16; c++) sum += w[c] * vm[c * 3 + d];
    out_v[i] = sum * inv + bv[o];
}

// ---------------------------------------------------------------------------
extern "C" void kernel_launch(void* const* d_in, const int* in_sizes, int n_in,
                              void* d_out, int out_size) {
    const float* s   = (const float*)d_in[0];
    const float* v   = (const float*)d_in[1];
    const void*  seg = d_in[2];
    const float* Ws  = (const float*)d_in[3];
    const float* bs  = (const float*)d_in[4];
    const float* Wv  = (const float*)d_in[5];
    const float* bv  = (const float*)d_in[6];
    float* out_s = (float*)d_out;
    float* out_v = out_s + (size_t)MM * CC;

    static int smem_set = 0;
    if (!smem_set) {
        cudaFuncSetAttribute(gemm_s_mma,
                             cudaFuncAttributeMaxDynamicSharedMemorySize, SMO_TOTAL);
        smem_set = 1;
    }

    probe_seg_kernel<<<1, 256>>>((const int*)seg);
    zero_kernel<<<2048, 256>>>();

    long long s_threads = (long long)NN * (CC / 4);
    scatter_s_kernel<<<(int)((s_threads + 255) / 256), 256>>>(s, seg);

    long long v_threads = (long long)NN * (VCD / 4);
    scatter_v_kernel<<<(int)((v_threads + 255) / 256), 256>>>(v, seg);

    dim3 gg(CC / 128, (MM + 127) / 128);
    gemm_s_mma<<<gg, 256, SMO_TOTAL>>>(Ws, bs, out_s);

    v_out_kernel<<<(MM * VCD + 255) / 256, 256>>>(Wv, bv, out_v);
}